// round 5
// baseline (speedup 1.0000x reference)
#include <cuda_runtime.h>
#include <cuda_fp16.h>
#include <math.h>

#define C_DIM 256
#define NROI  512
#define NBIN  49

// NHWC fp16 scratch, 4 levels (element offsets):
// lvl0 base 0 (2*256*256*256), lvl1 base 33554432, lvl2 base 41943040, lvl3 base 44040192
__device__ __half g_nhwc[44564480];

// -------------------------------------------------------------------------
// Fused NCHW -> NHWC(fp16) transpose, all 4 levels, one launch.
// 64c x 64hw tiles; float4 streaming loads (__ldcs), half2 stores.
// -------------------------------------------------------------------------
__global__ __launch_bounds__(256) void k_transpose(const float* __restrict__ p0,
                                                   const float* __restrict__ p1,
                                                   const float* __restrict__ p2,
                                                   const float* __restrict__ p3) {
    __shared__ float tile[64][65];

    int bid = blockIdx.x;
    int lvl;
    const float* __restrict__ in;
    size_t base;
    if (bid < 8192)       { lvl = 0; in = p0; base = 0ul; }
    else if (bid < 10240) { lvl = 1; in = p1; base = 33554432ul; bid -= 8192; }
    else if (bid < 10752) { lvl = 2; in = p2; base = 41943040ul; bid -= 10240; }
    else                  { lvl = 3; in = p3; base = 44040192ul; bid -= 10752; }

    const int Hs = 256 >> lvl;
    const int HW = Hs * Hs;
    const int hwTiles = HW >> 6;

    const int hwTile = bid % hwTiles;
    const int rest   = bid / hwTiles;
    const int cTile  = rest & 3;
    const int b      = rest >> 2;

    const int hw0 = hwTile << 6;
    const int c0  = cTile << 6;

    const int t  = threadIdx.x;
    const int tx = t & 15;    // hw group (float4)
    const int ty = t >> 4;    // c 0..15

    const float* __restrict__ ip =
        in + (size_t)b * C_DIM * HW + (size_t)c0 * HW + hw0;

#pragma unroll
    for (int k = 0; k < 4; k++) {
        const int c = ty + 16 * k;
        const float4 v = __ldcs((const float4*)(ip + (size_t)c * HW + 4 * tx));
        tile[c][4 * tx + 0] = v.x;
        tile[c][4 * tx + 1] = v.y;
        tile[c][4 * tx + 2] = v.z;
        tile[c][4 * tx + 3] = v.w;
    }
    __syncthreads();

    __half* __restrict__ op =
        g_nhwc + base + (size_t)b * HW * C_DIM + (size_t)hw0 * C_DIM + c0;

    const int c2 = t & 31;    // half2 channel-pair lane
    const int r0 = t >> 5;    // 8 row groups
#pragma unroll
    for (int k = 0; k < 8; k++) {
        const int row = r0 + 8 * k;
        const float a = tile[2 * c2 + 0][row];
        const float bfv = tile[2 * c2 + 1][row];
        ((half2*)(op + (size_t)row * C_DIM))[c2] = __floats2half2_rn(a, bfv);
    }
}

// -------------------------------------------------------------------------
// ROIAlign gather. Grid (512 rois, 2 chunks); each block does 128 channels.
// 256 threads = 8 warps; warp w handles bins w, w+8, ...; lane = 4 channels
// (uint2 = 4 fp16). 1024 CTAs keeps ~56 warps/SM resident.
// -------------------------------------------------------------------------
__global__ __launch_bounds__(256) void k_gather(const float* __restrict__ boxes,
                                                float* __restrict__ out) {
    __shared__ int   s_o[196][4];
    __shared__ float s_w[196][4];
    __shared__ float s_out[NBIN * 132];   // [bin][128ch], pitch 132 (float4-safe)

    const int tid = threadIdx.x;
    const int roi = blockIdx.x;
    const int c0  = blockIdx.y << 7;      // 0,128
    const int b   = roi >> 8;             // N = 256 boxes per batch

    const float bx1 = __ldg(boxes + roi * 4 + 0);
    const float by1 = __ldg(boxes + roi * 4 + 1);
    const float bx2 = __ldg(boxes + roi * 4 + 2);
    const float by2 = __ldg(boxes + roi * 4 + 3);

    const float size = sqrtf((bx2 - bx1) * (by2 - by1));
    int lvl = (int)floorf(4.0f + log2f(size / 224.0f + 1e-8f));
    lvl = max(2, min(5, lvl)) - 2;

    const int   H     = 256 >> lvl;
    const float scale = 0.25f / (float)(1 << lvl);
    const size_t base_off = ((lvl == 0) ? 0ul
                           : (lvl == 1) ? 33554432ul
                           : (lvl == 2) ? 41943040ul
                           :              44040192ul)
                          + (size_t)b * H * H * C_DIM;
    const __half* __restrict__ fb = g_nhwc + base_off + c0;

    const float x1s = bx1 * scale - 0.5f;
    const float y1s = by1 * scale - 0.5f;
    const float bw  = ((bx2 * scale - 0.5f) - x1s) * (1.0f / 7.0f);
    const float bh  = ((by2 * scale - 0.5f) - y1s) * (1.0f / 7.0f);

    if (tid < 196) {
        const int iy = tid / 14;
        const int ix = tid - iy * 14;
        const float ys = y1s + ((float)iy + 0.5f) * 0.5f * bh;
        const float xs = x1s + ((float)ix + 0.5f) * 0.5f * bw;
        const bool valid = (ys >= -1.0f) && (ys <= (float)H) &&
                           (xs >= -1.0f) && (xs <= (float)H);
        const float yc = fminf(fmaxf(ys, 0.0f), (float)(H - 1));
        const float xc = fminf(fmaxf(xs, 0.0f), (float)(H - 1));
        const int y0  = (int)floorf(yc);
        const int x0  = (int)floorf(xc);
        const int y1i = min(y0 + 1, H - 1);
        const int x1i = min(x0 + 1, H - 1);
        const float ly = yc - (float)y0, hy = 1.0f - ly;
        const float lx = xc - (float)x0, hx = 1.0f - lx;
        const float m = valid ? 0.25f : 0.0f;   // fold 2x2 mean
        s_w[tid][0] = hy * hx * m;
        s_w[tid][1] = hy * lx * m;
        s_w[tid][2] = ly * hx * m;
        s_w[tid][3] = ly * lx * m;
        const int r0 = y0 * H, r1 = y1i * H;
        s_o[tid][0] = (r0 + x0)  * C_DIM;
        s_o[tid][1] = (r0 + x1i) * C_DIM;
        s_o[tid][2] = (r1 + x0)  * C_DIM;
        s_o[tid][3] = (r1 + x1i) * C_DIM;
    }
    __syncthreads();

    const int warp = tid >> 5;
    const int lane = tid & 31;
    const int cl   = lane << 2;           // 4 channels per lane within chunk

    for (int bin = warp; bin < NBIN; bin += 8) {
        const int ph = bin / 7;
        const int pw = bin - ph * 7;
        float ax = 0.f, ay = 0.f, az = 0.f, aw = 0.f;
#pragma unroll
        for (int sy = 0; sy < 2; sy++) {
#pragma unroll
            for (int sx = 0; sx < 2; sx++) {
                const int s = (ph * 2 + sy) * 14 + (pw * 2 + sx);
                const float w0 = s_w[s][0], w1 = s_w[s][1];
                const float w2 = s_w[s][2], w3 = s_w[s][3];
                const uint2 r0 = *(const uint2*)(fb + s_o[s][0] + cl);
                const uint2 r1 = *(const uint2*)(fb + s_o[s][1] + cl);
                const uint2 r2 = *(const uint2*)(fb + s_o[s][2] + cl);
                const uint2 r3 = *(const uint2*)(fb + s_o[s][3] + cl);
                const float2 a0 = __half22float2(*(const half2*)&r0.x);
                const float2 b0 = __half22float2(*(const half2*)&r0.y);
                const float2 a1 = __half22float2(*(const half2*)&r1.x);
                const float2 b1 = __half22float2(*(const half2*)&r1.y);
                const float2 a2 = __half22float2(*(const half2*)&r2.x);
                const float2 b2 = __half22float2(*(const half2*)&r2.y);
                const float2 a3 = __half22float2(*(const half2*)&r3.x);
                const float2 b3 = __half22float2(*(const half2*)&r3.y);
                ax += w0 * a0.x + w1 * a1.x + w2 * a2.x + w3 * a3.x;
                ay += w0 * a0.y + w1 * a1.y + w2 * a2.y + w3 * a3.y;
                az += w0 * b0.x + w1 * b1.x + w2 * b2.x + w3 * b3.x;
                aw += w0 * b0.y + w1 * b1.y + w2 * b2.y + w3 * b3.y;
            }
        }
        *(float4*)(&s_out[bin * 132 + cl]) = make_float4(ax, ay, az, aw);
    }
    __syncthreads();

    // Write [c0..c0+127][49] region — contiguous 6272 floats, coalesced.
    float* __restrict__ og = out + (size_t)roi * (C_DIM * NBIN) + (size_t)c0 * NBIN;
    for (int e = tid; e < 128 * NBIN; e += 256) {
        const int ch  = e / NBIN;
        const int bin = e - ch * NBIN;
        og[e] = s_out[bin * 132 + ch];
    }
}

// -------------------------------------------------------------------------
extern "C" void kernel_launch(void* const* d_in, const int* in_sizes, int n_in,
                              void* d_out, int out_size) {
    const float* x2 = (const float*)d_in[0];   // [2,256,256,256]
    const float* x3 = (const float*)d_in[1];   // [2,256,128,128]
    const float* x4 = (const float*)d_in[2];   // [2,256, 64, 64]
    const float* x5 = (const float*)d_in[3];   // [2,256, 32, 32]
    const float* boxes = (const float*)d_in[4];// [2,256,4]
    float* out = (float*)d_out;                // [512,256,7,7]

    k_transpose<<<10880, 256>>>(x2, x3, x4, x5);
    dim3 ggrid(NROI, 2);
    k_gather<<<ggrid, 256>>>(boxes, out);
}

// round 6
// speedup vs baseline: 1.1815x; 1.1815x over previous
#include <cuda_runtime.h>
#include <cuda_fp16.h>
#include <math.h>

#define C_DIM 256
#define NROI  512
#define NBIN  49

// NHWC fp16 scratch, 4 levels (element offsets):
// lvl0 base 0 (2*256*256*256), lvl1 base 33554432, lvl2 base 41943040, lvl3 base 44040192
__device__ __half g_nhwc[44564480];

// Per-tile "needed" flags. Tile = 64 consecutive hw indices of one (lvl,b) plane.
// lvl0: 1024 tiles/batch ([0,2048)), lvl1: 256 ([2048,2560)),
// lvl2: 64 ([2560,2688)), lvl3: 16 ([2688,2720)).
#define NFLAGS 2720
__device__ unsigned char g_flags[NFLAGS];

__device__ __forceinline__ void roi_level(float bx1, float by1, float bx2, float by2,
                                          int& lvl, int& H, float& scale) {
    const float size = sqrtf((bx2 - bx1) * (by2 - by1));
    int l = (int)floorf(4.0f + log2f(size / 224.0f + 1e-8f));
    lvl = max(2, min(5, l)) - 2;
    H = 256 >> lvl;
    scale = 0.25f / (float)(1 << lvl);
}

// -------------------------------------------------------------------------
// Marker: zero flags, then mark every tile any ROI's samples can touch.
// One block, 1024 threads (thread = ROI for tid < 512).
// -------------------------------------------------------------------------
__global__ __launch_bounds__(1024) void k_mark(const float* __restrict__ boxes) {
    const int tid = threadIdx.x;
    for (int i = tid; i < NFLAGS; i += 1024) g_flags[i] = 0;
    __syncthreads();
    if (tid >= NROI) return;

    const int roi = tid;
    const int b   = roi >> 8;
    const float bx1 = boxes[roi * 4 + 0];
    const float by1 = boxes[roi * 4 + 1];
    const float bx2 = boxes[roi * 4 + 2];
    const float by2 = boxes[roi * 4 + 3];

    int lvl, H; float scale;
    roi_level(bx1, by1, bx2, by2, lvl, H, scale);

    const float x1s = bx1 * scale - 0.5f;
    const float y1s = by1 * scale - 0.5f;
    const float x2s = bx2 * scale - 0.5f;
    const float y2s = by2 * scale - 0.5f;

    // All sample coords lie in [x1s,x2s]x[y1s,y2s]; corners use clamp+floor(+1).
    const float Hm1 = (float)(H - 1);
    const int xa = (int)floorf(fminf(fmaxf(x1s, 0.0f), Hm1));
    const int xb = min((int)floorf(fminf(fmaxf(x2s, 0.0f), Hm1)) + 1, H - 1);
    const int ya = (int)floorf(fminf(fmaxf(y1s, 0.0f), Hm1));
    const int yb = min((int)floorf(fminf(fmaxf(y2s, 0.0f), Hm1)) + 1, H - 1);

    const int fbase   = (lvl == 0) ? 0 : (lvl == 1) ? 2048 : (lvl == 2) ? 2560 : 2688;
    const int tilesPB = (lvl == 0) ? 1024 : (lvl == 1) ? 256 : (lvl == 2) ? 64 : 16;
    unsigned char* fl = g_flags + fbase + b * tilesPB;

    for (int y = ya; y <= yb; y++) {
        const int t0 = (y * H + xa) >> 6;
        const int t1 = (y * H + xb) >> 6;
        for (int t = t0; t <= t1; t++) fl[t] = 1;
    }
}

// -------------------------------------------------------------------------
// Fused NCHW -> NHWC(fp16) transpose, all 4 levels, one launch.
// Skips tiles no ROI samples (flag==0).
// -------------------------------------------------------------------------
__global__ __launch_bounds__(256) void k_transpose(const float* __restrict__ p0,
                                                   const float* __restrict__ p1,
                                                   const float* __restrict__ p2,
                                                   const float* __restrict__ p3) {
    __shared__ float tile[64][65];

    int bid = blockIdx.x;
    int lvl;
    const float* __restrict__ in;
    size_t base;
    int fbase, tilesPB;
    if (bid < 8192)       { lvl = 0; in = p0; base = 0ul;         fbase = 0;    tilesPB = 1024; }
    else if (bid < 10240) { lvl = 1; in = p1; base = 33554432ul;  fbase = 2048; tilesPB = 256; bid -= 8192; }
    else if (bid < 10752) { lvl = 2; in = p2; base = 41943040ul;  fbase = 2560; tilesPB = 64;  bid -= 10240; }
    else                  { lvl = 3; in = p3; base = 44040192ul;  fbase = 2688; tilesPB = 16;  bid -= 10752; }

    const int Hs = 256 >> lvl;
    const int HW = Hs * Hs;
    const int hwTiles = HW >> 6;

    const int hwTile = bid % hwTiles;
    const int rest   = bid / hwTiles;
    const int cTile  = rest & 3;
    const int b      = rest >> 2;

    if (g_flags[fbase + b * tilesPB + hwTile] == 0) return;

    const int hw0 = hwTile << 6;
    const int c0  = cTile << 6;

    const int t  = threadIdx.x;
    const int tx = t & 15;    // hw group (float4)
    const int ty = t >> 4;    // c 0..15

    const float* __restrict__ ip =
        in + (size_t)b * C_DIM * HW + (size_t)c0 * HW + hw0;

#pragma unroll
    for (int k = 0; k < 4; k++) {
        const int c = ty + 16 * k;
        const float4 v = __ldcs((const float4*)(ip + (size_t)c * HW + 4 * tx));
        tile[c][4 * tx + 0] = v.x;
        tile[c][4 * tx + 1] = v.y;
        tile[c][4 * tx + 2] = v.z;
        tile[c][4 * tx + 3] = v.w;
    }
    __syncthreads();

    __half* __restrict__ op =
        g_nhwc + base + (size_t)b * HW * C_DIM + (size_t)hw0 * C_DIM + c0;

    const int c2 = t & 31;    // half2 channel-pair lane
    const int r0 = t >> 5;    // 8 row groups
#pragma unroll
    for (int k = 0; k < 8; k++) {
        const int row = r0 + 8 * k;
        const float a = tile[2 * c2 + 0][row];
        const float bfv = tile[2 * c2 + 1][row];
        ((half2*)(op + (size_t)row * C_DIM))[c2] = __floats2half2_rn(a, bfv);
    }
}

// -------------------------------------------------------------------------
// ROIAlign gather. Grid (512 rois, 4 chunks); each block does 64 channels.
// 256 threads = 8 warps; warp w handles bins w, w+8, ...; lane = half2 pair.
// (Round-4 configuration: measured 34.1us, occ 78%.)
// -------------------------------------------------------------------------
__global__ __launch_bounds__(256) void k_gather(const float* __restrict__ boxes,
                                                float* __restrict__ out) {
    __shared__ int   s_o[196][4];
    __shared__ float s_w[196][4];
    __shared__ float s_out[NBIN * 66];    // [bin][64ch], pitch 66 (float2-safe)

    const int tid = threadIdx.x;
    const int roi = blockIdx.x;
    const int c0  = blockIdx.y << 6;      // 0,64,128,192
    const int b   = roi >> 8;             // N = 256 boxes per batch

    const float bx1 = __ldg(boxes + roi * 4 + 0);
    const float by1 = __ldg(boxes + roi * 4 + 1);
    const float bx2 = __ldg(boxes + roi * 4 + 2);
    const float by2 = __ldg(boxes + roi * 4 + 3);

    int lvl, H; float scale;
    roi_level(bx1, by1, bx2, by2, lvl, H, scale);

    const size_t base_off = ((lvl == 0) ? 0ul
                           : (lvl == 1) ? 33554432ul
                           : (lvl == 2) ? 41943040ul
                           :              44040192ul)
                          + (size_t)b * H * H * C_DIM;
    const __half* __restrict__ fb = g_nhwc + base_off + c0;

    const float x1s = bx1 * scale - 0.5f;
    const float y1s = by1 * scale - 0.5f;
    const float bw  = ((bx2 * scale - 0.5f) - x1s) * (1.0f / 7.0f);
    const float bh  = ((by2 * scale - 0.5f) - y1s) * (1.0f / 7.0f);

    if (tid < 196) {
        const int iy = tid / 14;
        const int ix = tid - iy * 14;
        const float ys = y1s + ((float)iy + 0.5f) * 0.5f * bh;
        const float xs = x1s + ((float)ix + 0.5f) * 0.5f * bw;
        const bool valid = (ys >= -1.0f) && (ys <= (float)H) &&
                           (xs >= -1.0f) && (xs <= (float)H);
        const float yc = fminf(fmaxf(ys, 0.0f), (float)(H - 1));
        const float xc = fminf(fmaxf(xs, 0.0f), (float)(H - 1));
        const int y0  = (int)floorf(yc);
        const int x0  = (int)floorf(xc);
        const int y1i = min(y0 + 1, H - 1);
        const int x1i = min(x0 + 1, H - 1);
        const float ly = yc - (float)y0, hy = 1.0f - ly;
        const float lx = xc - (float)x0, hx = 1.0f - lx;
        const float m = valid ? 0.25f : 0.0f;   // fold 2x2 mean
        s_w[tid][0] = hy * hx * m;
        s_w[tid][1] = hy * lx * m;
        s_w[tid][2] = ly * hx * m;
        s_w[tid][3] = ly * lx * m;
        const int r0 = y0 * H, r1 = y1i * H;
        s_o[tid][0] = (r0 + x0)  * C_DIM;
        s_o[tid][1] = (r0 + x1i) * C_DIM;
        s_o[tid][2] = (r1 + x0)  * C_DIM;
        s_o[tid][3] = (r1 + x1i) * C_DIM;
    }
    __syncthreads();

    const int warp = tid >> 5;
    const int lane = tid & 31;
    const int cl   = lane << 1;           // channel pair within 64-ch chunk

    for (int bin = warp; bin < NBIN; bin += 8) {
        const int ph = bin / 7;
        const int pw = bin - ph * 7;
        float ax = 0.f, ay = 0.f;
#pragma unroll
        for (int sy = 0; sy < 2; sy++) {
#pragma unroll
            for (int sx = 0; sx < 2; sx++) {
                const int s = (ph * 2 + sy) * 14 + (pw * 2 + sx);
                const float w0 = s_w[s][0], w1 = s_w[s][1];
                const float w2 = s_w[s][2], w3 = s_w[s][3];
                const float2 v0 = __half22float2(*(const half2*)(fb + s_o[s][0] + cl));
                const float2 v1 = __half22float2(*(const half2*)(fb + s_o[s][1] + cl));
                const float2 v2 = __half22float2(*(const half2*)(fb + s_o[s][2] + cl));
                const float2 v3 = __half22float2(*(const half2*)(fb + s_o[s][3] + cl));
                ax += w0 * v0.x + w1 * v1.x + w2 * v2.x + w3 * v3.x;
                ay += w0 * v0.y + w1 * v1.y + w2 * v2.y + w3 * v3.y;
            }
        }
        *(float2*)(&s_out[bin * 66 + cl]) = make_float2(ax, ay);
    }
    __syncthreads();

    // Write [c0..c0+63][49] region — contiguous 3136 floats, coalesced.
    float* __restrict__ og = out + (size_t)roi * (C_DIM * NBIN) + (size_t)c0 * NBIN;
    for (int e = tid; e < 64 * NBIN; e += 256) {
        const int ch  = e / NBIN;
        const int bin = e - ch * NBIN;
        og[e] = s_out[bin * 66 + ch];
    }
}

// -------------------------------------------------------------------------
extern "C" void kernel_launch(void* const* d_in, const int* in_sizes, int n_in,
                              void* d_out, int out_size) {
    const float* x2 = (const float*)d_in[0];   // [2,256,256,256]
    const float* x3 = (const float*)d_in[1];   // [2,256,128,128]
    const float* x4 = (const float*)d_in[2];   // [2,256, 64, 64]
    const float* x5 = (const float*)d_in[3];   // [2,256, 32, 32]
    const float* boxes = (const float*)d_in[4];// [2,256,4]
    float* out = (float*)d_out;                // [512,256,7,7]

    k_mark<<<1, 1024>>>(boxes);
    k_transpose<<<10880, 256>>>(x2, x3, x4, x5);
    dim3 ggrid(NROI, 4);
    k_gather<<<ggrid, 256>>>(boxes, out);
}

// round 7
// speedup vs baseline: 1.3753x; 1.1640x over previous
#include <cuda_runtime.h>
#include <cuda_fp16.h>
#include <math.h>

#define C_DIM 256
#define NROI  512
#define NBIN  49

// NHWC fp16 scratch, 4 levels (element offsets):
// lvl0 base 0 (2*256*256*256), lvl1 base 33554432, lvl2 base 41943040, lvl3 base 44040192
__device__ __half g_nhwc[44564480];

// Per-tile "needed" flags. Tile = 64 consecutive hw indices of one (lvl,b) plane.
// lvl0: 1024 tiles/batch ([0,2048)), lvl1: 256 ([2048,2560)),
// lvl2: 64 ([2560,2688)), lvl3: 16 ([2688,2720)).
#define NFLAGS 2720
__device__ unsigned char g_flags[NFLAGS];

__device__ __forceinline__ void roi_level(float bx1, float by1, float bx2, float by2,
                                          int& lvl, int& H, float& scale) {
    const float size = sqrtf((bx2 - bx1) * (by2 - by1));
    int l = (int)floorf(4.0f + log2f(size / 224.0f + 1e-8f));
    lvl = max(2, min(5, l)) - 2;
    H = 256 >> lvl;
    scale = 0.25f / (float)(1 << lvl);
}

// -------------------------------------------------------------------------
// Marker: one block per ROI (64 threads); thread = feature row. Flags are
// pre-zeroed by cudaMemsetAsync. Marks every 64-hw tile the ROI can sample.
// -------------------------------------------------------------------------
__global__ __launch_bounds__(64) void k_mark(const float* __restrict__ boxes) {
    const int roi = blockIdx.x;
    const int b   = roi >> 8;
    const float bx1 = __ldg(boxes + roi * 4 + 0);
    const float by1 = __ldg(boxes + roi * 4 + 1);
    const float bx2 = __ldg(boxes + roi * 4 + 2);
    const float by2 = __ldg(boxes + roi * 4 + 3);

    int lvl, H; float scale;
    roi_level(bx1, by1, bx2, by2, lvl, H, scale);

    const float x1s = bx1 * scale - 0.5f;
    const float y1s = by1 * scale - 0.5f;
    const float x2s = bx2 * scale - 0.5f;
    const float y2s = by2 * scale - 0.5f;

    // All sample coords lie in [x1s,x2s]x[y1s,y2s]; corners use clamp+floor(+1).
    const float Hm1 = (float)(H - 1);
    const int xa = (int)floorf(fminf(fmaxf(x1s, 0.0f), Hm1));
    const int xb = min((int)floorf(fminf(fmaxf(x2s, 0.0f), Hm1)) + 1, H - 1);
    const int ya = (int)floorf(fminf(fmaxf(y1s, 0.0f), Hm1));
    const int yb = min((int)floorf(fminf(fmaxf(y2s, 0.0f), Hm1)) + 1, H - 1);

    const int fbase   = (lvl == 0) ? 0 : (lvl == 1) ? 2048 : (lvl == 2) ? 2560 : 2688;
    const int tilesPB = (lvl == 0) ? 1024 : (lvl == 1) ? 256 : (lvl == 2) ? 64 : 16;
    unsigned char* fl = g_flags + fbase + b * tilesPB;

    for (int y = ya + (int)threadIdx.x; y <= yb; y += 64) {
        const int t0 = (y * H + xa) >> 6;
        const int t1 = (y * H + xb) >> 6;
        for (int t = t0; t <= t1; t++) fl[t] = 1;
    }
}

// -------------------------------------------------------------------------
// Fused NCHW -> NHWC(fp16) transpose, all 4 levels, one launch.
// Skips tiles no ROI samples (flag==0).
// -------------------------------------------------------------------------
__global__ __launch_bounds__(256) void k_transpose(const float* __restrict__ p0,
                                                   const float* __restrict__ p1,
                                                   const float* __restrict__ p2,
                                                   const float* __restrict__ p3) {
    __shared__ float tile[64][65];

    int bid = blockIdx.x;
    int lvl;
    const float* __restrict__ in;
    size_t base;
    int fbase, tilesPB;
    if (bid < 8192)       { lvl = 0; in = p0; base = 0ul;         fbase = 0;    tilesPB = 1024; }
    else if (bid < 10240) { lvl = 1; in = p1; base = 33554432ul;  fbase = 2048; tilesPB = 256; bid -= 8192; }
    else if (bid < 10752) { lvl = 2; in = p2; base = 41943040ul;  fbase = 2560; tilesPB = 64;  bid -= 10240; }
    else                  { lvl = 3; in = p3; base = 44040192ul;  fbase = 2688; tilesPB = 16;  bid -= 10752; }

    const int Hs = 256 >> lvl;
    const int HW = Hs * Hs;
    const int hwTiles = HW >> 6;

    const int hwTile = bid % hwTiles;
    const int rest   = bid / hwTiles;
    const int cTile  = rest & 3;
    const int b      = rest >> 2;

    if (g_flags[fbase + b * tilesPB + hwTile] == 0) return;

    const int hw0 = hwTile << 6;
    const int c0  = cTile << 6;

    const int t  = threadIdx.x;
    const int tx = t & 15;    // hw group (float4)
    const int ty = t >> 4;    // c 0..15

    const float* __restrict__ ip =
        in + (size_t)b * C_DIM * HW + (size_t)c0 * HW + hw0;

#pragma unroll
    for (int k = 0; k < 4; k++) {
        const int c = ty + 16 * k;
        const float4 v = __ldcs((const float4*)(ip + (size_t)c * HW + 4 * tx));
        tile[c][4 * tx + 0] = v.x;
        tile[c][4 * tx + 1] = v.y;
        tile[c][4 * tx + 2] = v.z;
        tile[c][4 * tx + 3] = v.w;
    }
    __syncthreads();

    __half* __restrict__ op =
        g_nhwc + base + (size_t)b * HW * C_DIM + (size_t)hw0 * C_DIM + c0;

    const int c2 = t & 31;    // half2 channel-pair lane
    const int r0 = t >> 5;    // 8 row groups
#pragma unroll
    for (int k = 0; k < 8; k++) {
        const int row = r0 + 8 * k;
        const float a = tile[2 * c2 + 0][row];
        const float bfv = tile[2 * c2 + 1][row];
        ((half2*)(op + (size_t)row * C_DIM))[c2] = __floats2half2_rn(a, bfv);
    }
}

// -------------------------------------------------------------------------
// ROIAlign gather. Grid (512 rois, 4 chunks); each block does 64 channels.
// 256 threads = 8 warps; warp w handles bins w, w+8, ...; lane = half2 pair.
// (Round-4 configuration: measured 34.1us, occ 78%.)
// -------------------------------------------------------------------------
__global__ __launch_bounds__(256) void k_gather(const float* __restrict__ boxes,
                                                float* __restrict__ out) {
    __shared__ int   s_o[196][4];
    __shared__ float s_w[196][4];
    __shared__ float s_out[NBIN * 66];    // [bin][64ch], pitch 66 (float2-safe)

    const int tid = threadIdx.x;
    const int roi = blockIdx.x;
    const int c0  = blockIdx.y << 6;      // 0,64,128,192
    const int b   = roi >> 8;             // N = 256 boxes per batch

    const float bx1 = __ldg(boxes + roi * 4 + 0);
    const float by1 = __ldg(boxes + roi * 4 + 1);
    const float bx2 = __ldg(boxes + roi * 4 + 2);
    const float by2 = __ldg(boxes + roi * 4 + 3);

    int lvl, H; float scale;
    roi_level(bx1, by1, bx2, by2, lvl, H, scale);

    const size_t base_off = ((lvl == 0) ? 0ul
                           : (lvl == 1) ? 33554432ul
                           : (lvl == 2) ? 41943040ul
                           :              44040192ul)
                          + (size_t)b * H * H * C_DIM;
    const __half* __restrict__ fb = g_nhwc + base_off + c0;

    const float x1s = bx1 * scale - 0.5f;
    const float y1s = by1 * scale - 0.5f;
    const float bw  = ((bx2 * scale - 0.5f) - x1s) * (1.0f / 7.0f);
    const float bh  = ((by2 * scale - 0.5f) - y1s) * (1.0f / 7.0f);

    if (tid < 196) {
        const int iy = tid / 14;
        const int ix = tid - iy * 14;
        const float ys = y1s + ((float)iy + 0.5f) * 0.5f * bh;
        const float xs = x1s + ((float)ix + 0.5f) * 0.5f * bw;
        const bool valid = (ys >= -1.0f) && (ys <= (float)H) &&
                           (xs >= -1.0f) && (xs <= (float)H);
        const float yc = fminf(fmaxf(ys, 0.0f), (float)(H - 1));
        const float xc = fminf(fmaxf(xs, 0.0f), (float)(H - 1));
        const int y0  = (int)floorf(yc);
        const int x0  = (int)floorf(xc);
        const int y1i = min(y0 + 1, H - 1);
        const int x1i = min(x0 + 1, H - 1);
        const float ly = yc - (float)y0, hy = 1.0f - ly;
        const float lx = xc - (float)x0, hx = 1.0f - lx;
        const float m = valid ? 0.25f : 0.0f;   // fold 2x2 mean
        s_w[tid][0] = hy * hx * m;
        s_w[tid][1] = hy * lx * m;
        s_w[tid][2] = ly * hx * m;
        s_w[tid][3] = ly * lx * m;
        const int r0 = y0 * H, r1 = y1i * H;
        s_o[tid][0] = (r0 + x0)  * C_DIM;
        s_o[tid][1] = (r0 + x1i) * C_DIM;
        s_o[tid][2] = (r1 + x0)  * C_DIM;
        s_o[tid][3] = (r1 + x1i) * C_DIM;
    }
    __syncthreads();

    const int warp = tid >> 5;
    const int lane = tid & 31;
    const int cl   = lane << 1;           // channel pair within 64-ch chunk

    for (int bin = warp; bin < NBIN; bin += 8) {
        const int ph = bin / 7;
        const int pw = bin - ph * 7;
        float ax = 0.f, ay = 0.f;
#pragma unroll
        for (int sy = 0; sy < 2; sy++) {
#pragma unroll
            for (int sx = 0; sx < 2; sx++) {
                const int s = (ph * 2 + sy) * 14 + (pw * 2 + sx);
                const float w0 = s_w[s][0], w1 = s_w[s][1];
                const float w2 = s_w[s][2], w3 = s_w[s][3];
                const float2 v0 = __half22float2(*(const half2*)(fb + s_o[s][0] + cl));
                const float2 v1 = __half22float2(*(const half2*)(fb + s_o[s][1] + cl));
                const float2 v2 = __half22float2(*(const half2*)(fb + s_o[s][2] + cl));
                const float2 v3 = __half22float2(*(const half2*)(fb + s_o[s][3] + cl));
                ax += w0 * v0.x + w1 * v1.x + w2 * v2.x + w3 * v3.x;
                ay += w0 * v0.y + w1 * v1.y + w2 * v2.y + w3 * v3.y;
            }
        }
        *(float2*)(&s_out[bin * 66 + cl]) = make_float2(ax, ay);
    }
    __syncthreads();

    // Write [c0..c0+63][49] region — contiguous 3136 floats, coalesced.
    float* __restrict__ og = out + (size_t)roi * (C_DIM * NBIN) + (size_t)c0 * NBIN;
    for (int e = tid; e < 64 * NBIN; e += 256) {
        const int ch  = e / NBIN;
        const int bin = e - ch * NBIN;
        og[e] = s_out[bin * 66 + ch];
    }
}

// -------------------------------------------------------------------------
extern "C" void kernel_launch(void* const* d_in, const int* in_sizes, int n_in,
                              void* d_out, int out_size) {
    const float* x2 = (const float*)d_in[0];   // [2,256,256,256]
    const float* x3 = (const float*)d_in[1];   // [2,256,128,128]
    const float* x4 = (const float*)d_in[2];   // [2,256, 64, 64]
    const float* x5 = (const float*)d_in[3];   // [2,256, 32, 32]
    const float* boxes = (const float*)d_in[4];// [2,256,4]
    float* out = (float*)d_out;                // [512,256,7,7]

    void* flags_ptr = nullptr;
    cudaGetSymbolAddress(&flags_ptr, g_flags);
    cudaMemsetAsync(flags_ptr, 0, NFLAGS);     // async, graph-capturable

    k_mark<<<NROI, 64>>>(boxes);
    k_transpose<<<10880, 256>>>(x2, x3, x4, x5);
    dim3 ggrid(NROI, 4);
    k_gather<<<ggrid, 256>>>(boxes, out);
}

// round 8
// speedup vs baseline: 1.3824x; 1.0051x over previous
#include <cuda_runtime.h>
#include <cuda_fp16.h>
#include <math.h>

#define C_DIM 256
#define NROI  512
#define NBIN  49

// NHWC fp16 scratch, 4 levels (element offsets):
// lvl0 base 0 (2*256*256*256), lvl1 base 33554432, lvl2 base 41943040, lvl3 base 44040192
__device__ __half g_nhwc[44564480];

// Per-tile "needed" flags. Tile = 64 consecutive hw indices of one (lvl,b) plane.
#define NFLAGS 2720
__device__ unsigned char g_flags[NFLAGS];

__device__ __forceinline__ void roi_level(float bx1, float by1, float bx2, float by2,
                                          int& lvl, int& H, float& scale) {
    const float size = sqrtf((bx2 - bx1) * (by2 - by1));
    int l = (int)floorf(4.0f + log2f(size / 224.0f + 1e-8f));
    lvl = max(2, min(5, l)) - 2;
    H = 256 >> lvl;
    scale = 0.25f / (float)(1 << lvl);
}

// -------------------------------------------------------------------------
// Marker: one block per ROI (64 threads); thread = feature row. Flags are
// pre-zeroed by cudaMemsetAsync. Marks every 64-hw tile the ROI can sample.
// -------------------------------------------------------------------------
__global__ __launch_bounds__(64) void k_mark(const float* __restrict__ boxes) {
    const int roi = blockIdx.x;
    const int b   = roi >> 8;
    const float bx1 = __ldg(boxes + roi * 4 + 0);
    const float by1 = __ldg(boxes + roi * 4 + 1);
    const float bx2 = __ldg(boxes + roi * 4 + 2);
    const float by2 = __ldg(boxes + roi * 4 + 3);

    int lvl, H; float scale;
    roi_level(bx1, by1, bx2, by2, lvl, H, scale);

    const float x1s = bx1 * scale - 0.5f;
    const float y1s = by1 * scale - 0.5f;
    const float x2s = bx2 * scale - 0.5f;
    const float y2s = by2 * scale - 0.5f;

    const float Hm1 = (float)(H - 1);
    const int xa = (int)floorf(fminf(fmaxf(x1s, 0.0f), Hm1));
    const int xb = min((int)floorf(fminf(fmaxf(x2s, 0.0f), Hm1)) + 1, H - 1);
    const int ya = (int)floorf(fminf(fmaxf(y1s, 0.0f), Hm1));
    const int yb = min((int)floorf(fminf(fmaxf(y2s, 0.0f), Hm1)) + 1, H - 1);

    const int fbase   = (lvl == 0) ? 0 : (lvl == 1) ? 2048 : (lvl == 2) ? 2560 : 2688;
    const int tilesPB = (lvl == 0) ? 1024 : (lvl == 1) ? 256 : (lvl == 2) ? 64 : 16;
    unsigned char* fl = g_flags + fbase + b * tilesPB;

    for (int y = ya + (int)threadIdx.x; y <= yb; y += 64) {
        const int t0 = (y * H + xa) >> 6;
        const int t1 = (y * H + xb) >> 6;
        for (int t = t0; t <= t1; t++) fl[t] = 1;
    }
}

// -------------------------------------------------------------------------
// Fused NCHW -> NHWC(fp16) transpose, all 4 levels, one launch.
// Skips tiles no ROI samples (flag==0).
// -------------------------------------------------------------------------
__global__ __launch_bounds__(256) void k_transpose(const float* __restrict__ p0,
                                                   const float* __restrict__ p1,
                                                   const float* __restrict__ p2,
                                                   const float* __restrict__ p3) {
    __shared__ float tile[64][65];

    int bid = blockIdx.x;
    int lvl;
    const float* __restrict__ in;
    size_t base;
    int fbase, tilesPB;
    if (bid < 8192)       { lvl = 0; in = p0; base = 0ul;         fbase = 0;    tilesPB = 1024; }
    else if (bid < 10240) { lvl = 1; in = p1; base = 33554432ul;  fbase = 2048; tilesPB = 256; bid -= 8192; }
    else if (bid < 10752) { lvl = 2; in = p2; base = 41943040ul;  fbase = 2560; tilesPB = 64;  bid -= 10240; }
    else                  { lvl = 3; in = p3; base = 44040192ul;  fbase = 2688; tilesPB = 16;  bid -= 10752; }

    const int Hs = 256 >> lvl;
    const int HW = Hs * Hs;
    const int hwTiles = HW >> 6;

    const int hwTile = bid % hwTiles;
    const int rest   = bid / hwTiles;
    const int cTile  = rest & 3;
    const int b      = rest >> 2;

    if (g_flags[fbase + b * tilesPB + hwTile] == 0) return;

    const int hw0 = hwTile << 6;
    const int c0  = cTile << 6;

    const int t  = threadIdx.x;
    const int tx = t & 15;    // hw group (float4)
    const int ty = t >> 4;    // c 0..15

    const float* __restrict__ ip =
        in + (size_t)b * C_DIM * HW + (size_t)c0 * HW + hw0;

#pragma unroll
    for (int k = 0; k < 4; k++) {
        const int c = ty + 16 * k;
        const float4 v = __ldcs((const float4*)(ip + (size_t)c * HW + 4 * tx));
        tile[c][4 * tx + 0] = v.x;
        tile[c][4 * tx + 1] = v.y;
        tile[c][4 * tx + 2] = v.z;
        tile[c][4 * tx + 3] = v.w;
    }
    __syncthreads();

    __half* __restrict__ op =
        g_nhwc + base + (size_t)b * HW * C_DIM + (size_t)hw0 * C_DIM + c0;

    const int c2 = t & 31;    // half2 channel-pair lane
    const int r0 = t >> 5;    // 8 row groups
#pragma unroll
    for (int k = 0; k < 8; k++) {
        const int row = r0 + 8 * k;
        const float a = tile[2 * c2 + 0][row];
        const float bfv = tile[2 * c2 + 1][row];
        ((half2*)(op + (size_t)row * C_DIM))[c2] = __floats2half2_rn(a, bfv);
    }
}

// -------------------------------------------------------------------------
// ROIAlign gather. Grid (512 rois, 4 chunks); each block does 64 channels.
// Inner loop: per-sample 4-corner sum in half2 (HMUL2+3xHFMA2), fp32
// cross-sample accumulation. Weights (x4 half2) and offsets (int4) packed
// for single LDS.128 each.
// -------------------------------------------------------------------------
__global__ __launch_bounds__(256) void k_gather(const float* __restrict__ boxes,
                                                float* __restrict__ out) {
    __shared__ int4  s_oq[196];           // 4 corner offsets
    __shared__ uint4 s_wq[196];           // 4 weights as packed half2 pairs
    __shared__ float s_out[NBIN * 66];    // [bin][64ch], pitch 66 (float2-safe)

    const int tid = threadIdx.x;
    const int roi = blockIdx.x;
    const int c0  = blockIdx.y << 6;      // 0,64,128,192
    const int b   = roi >> 8;             // N = 256 boxes per batch

    const float bx1 = __ldg(boxes + roi * 4 + 0);
    const float by1 = __ldg(boxes + roi * 4 + 1);
    const float bx2 = __ldg(boxes + roi * 4 + 2);
    const float by2 = __ldg(boxes + roi * 4 + 3);

    int lvl, H; float scale;
    roi_level(bx1, by1, bx2, by2, lvl, H, scale);

    const size_t base_off = ((lvl == 0) ? 0ul
                           : (lvl == 1) ? 33554432ul
                           : (lvl == 2) ? 41943040ul
                           :              44040192ul)
                          + (size_t)b * H * H * C_DIM;
    const __half* __restrict__ fb = g_nhwc + base_off + c0;

    const float x1s = bx1 * scale - 0.5f;
    const float y1s = by1 * scale - 0.5f;
    const float bw  = ((bx2 * scale - 0.5f) - x1s) * (1.0f / 7.0f);
    const float bh  = ((by2 * scale - 0.5f) - y1s) * (1.0f / 7.0f);

    if (tid < 196) {
        const int iy = tid / 14;
        const int ix = tid - iy * 14;
        const float ys = y1s + ((float)iy + 0.5f) * 0.5f * bh;
        const float xs = x1s + ((float)ix + 0.5f) * 0.5f * bw;
        const bool valid = (ys >= -1.0f) && (ys <= (float)H) &&
                           (xs >= -1.0f) && (xs <= (float)H);
        const float yc = fminf(fmaxf(ys, 0.0f), (float)(H - 1));
        const float xc = fminf(fmaxf(xs, 0.0f), (float)(H - 1));
        const int y0  = (int)floorf(yc);
        const int x0  = (int)floorf(xc);
        const int y1i = min(y0 + 1, H - 1);
        const int x1i = min(x0 + 1, H - 1);
        const float ly = yc - (float)y0, hy = 1.0f - ly;
        const float lx = xc - (float)x0, hx = 1.0f - lx;
        const float m = valid ? 0.25f : 0.0f;   // fold 2x2 mean
        const half2 w0 = __float2half2_rn(hy * hx * m);
        const half2 w1 = __float2half2_rn(hy * lx * m);
        const half2 w2 = __float2half2_rn(ly * hx * m);
        const half2 w3 = __float2half2_rn(ly * lx * m);
        uint4 wq;
        wq.x = *(const unsigned int*)&w0;
        wq.y = *(const unsigned int*)&w1;
        wq.z = *(const unsigned int*)&w2;
        wq.w = *(const unsigned int*)&w3;
        s_wq[tid] = wq;
        const int r0 = y0 * H, r1 = y1i * H;
        int4 oq;
        oq.x = (r0 + x0)  * C_DIM;
        oq.y = (r0 + x1i) * C_DIM;
        oq.z = (r1 + x0)  * C_DIM;
        oq.w = (r1 + x1i) * C_DIM;
        s_oq[tid] = oq;
    }
    __syncthreads();

    const int warp = tid >> 5;
    const int lane = tid & 31;
    const int cl   = lane << 1;           // channel pair within 64-ch chunk

    for (int bin = warp; bin < NBIN; bin += 8) {
        const int ph = bin / 7;
        const int pw = bin - ph * 7;
        float ax = 0.f, ay = 0.f;
#pragma unroll
        for (int sy = 0; sy < 2; sy++) {
#pragma unroll
            for (int sx = 0; sx < 2; sx++) {
                const int s = (ph * 2 + sy) * 14 + (pw * 2 + sx);
                const uint4 wq = s_wq[s];
                const int4  oq = s_oq[s];
                const half2 w0 = *(const half2*)&wq.x;
                const half2 w1 = *(const half2*)&wq.y;
                const half2 w2 = *(const half2*)&wq.z;
                const half2 w3 = *(const half2*)&wq.w;
                const half2 v0 = *(const half2*)(fb + oq.x + cl);
                const half2 v1 = *(const half2*)(fb + oq.y + cl);
                const half2 v2 = *(const half2*)(fb + oq.z + cl);
                const half2 v3 = *(const half2*)(fb + oq.w + cl);
                half2 acc = __hmul2(w0, v0);
                acc = __hfma2(w1, v1, acc);
                acc = __hfma2(w2, v2, acc);
                acc = __hfma2(w3, v3, acc);
                const float2 f = __half22float2(acc);
                ax += f.x;
                ay += f.y;
            }
        }
        *(float2*)(&s_out[bin * 66 + cl]) = make_float2(ax, ay);
    }
    __syncthreads();

    // Write [c0..c0+63][49] region — contiguous 3136 floats, coalesced.
    float* __restrict__ og = out + (size_t)roi * (C_DIM * NBIN) + (size_t)c0 * NBIN;
    for (int e = tid; e < 64 * NBIN; e += 256) {
        const int ch  = e / NBIN;
        const int bin = e - ch * NBIN;
        og[e] = s_out[bin * 66 + ch];
    }
}

// -------------------------------------------------------------------------
extern "C" void kernel_launch(void* const* d_in, const int* in_sizes, int n_in,
                              void* d_out, int out_size) {
    const float* x2 = (const float*)d_in[0];   // [2,256,256,256]
    const float* x3 = (const float*)d_in[1];   // [2,256,128,128]
    const float* x4 = (const float*)d_in[2];   // [2,256, 64, 64]
    const float* x5 = (const float*)d_in[3];   // [2,256, 32, 32]
    const float* boxes = (const float*)d_in[4];// [2,256,4]
    float* out = (float*)d_out;                // [512,256,7,7]

    void* flags_ptr = nullptr;
    cudaGetSymbolAddress(&flags_ptr, g_flags);
    cudaMemsetAsync(flags_ptr, 0, NFLAGS);     // async, graph-capturable

    k_mark<<<NROI, 64>>>(boxes);
    k_transpose<<<10880, 256>>>(x2, x3, x4, x5);
    dim3 ggrid(NROI, 4);
    k_gather<<<ggrid, 256>>>(boxes, out);
}

// round 9
// speedup vs baseline: 1.3902x; 1.0056x over previous
#include <cuda_runtime.h>
#include <cuda_fp16.h>
#include <math.h>

#define C_DIM 256
#define NROI  512
#define NBIN  49

// NHWC fp16 scratch, 4 levels (element offsets):
// lvl0 base 0 (2*256*256*256), lvl1 base 33554432, lvl2 base 41943040, lvl3 base 44040192
__device__ __half g_nhwc[44564480];

// Per-tile "needed" flags.
// lvl0: 16-px hw tiles -> 4096/batch, region [0, 8192)
// lvl1: 64-px -> 256/batch, [8192, 8704)
// lvl2: 64-px -> 64/batch,  [8704, 8832)
// lvl3: 64-px -> 16/batch,  [8832, 8864)
#define NFLAGS 8864
__device__ unsigned char g_flags[NFLAGS];

__device__ __forceinline__ void roi_level(float bx1, float by1, float bx2, float by2,
                                          int& lvl, int& H, float& scale) {
    const float size = sqrtf((bx2 - bx1) * (by2 - by1));
    int l = (int)floorf(4.0f + log2f(size / 224.0f + 1e-8f));
    lvl = max(2, min(5, l)) - 2;
    H = 256 >> lvl;
    scale = 0.25f / (float)(1 << lvl);
}

// -------------------------------------------------------------------------
// Marker: one block per ROI (64 threads); thread = feature row.
// lvl0 marks 16-px tiles, others 64-px. Flags pre-zeroed by cudaMemsetAsync.
// -------------------------------------------------------------------------
__global__ __launch_bounds__(64) void k_mark(const float* __restrict__ boxes) {
    const int roi = blockIdx.x;
    const int b   = roi >> 8;
    const float bx1 = __ldg(boxes + roi * 4 + 0);
    const float by1 = __ldg(boxes + roi * 4 + 1);
    const float bx2 = __ldg(boxes + roi * 4 + 2);
    const float by2 = __ldg(boxes + roi * 4 + 3);

    int lvl, H; float scale;
    roi_level(bx1, by1, bx2, by2, lvl, H, scale);

    const float x1s = bx1 * scale - 0.5f;
    const float y1s = by1 * scale - 0.5f;
    const float x2s = bx2 * scale - 0.5f;
    const float y2s = by2 * scale - 0.5f;

    const float Hm1 = (float)(H - 1);
    const int xa = (int)floorf(fminf(fmaxf(x1s, 0.0f), Hm1));
    const int xb = min((int)floorf(fminf(fmaxf(x2s, 0.0f), Hm1)) + 1, H - 1);
    const int ya = (int)floorf(fminf(fmaxf(y1s, 0.0f), Hm1));
    const int yb = min((int)floorf(fminf(fmaxf(y2s, 0.0f), Hm1)) + 1, H - 1);

    const int fbase   = (lvl == 0) ? 0 : (lvl == 1) ? 8192 : (lvl == 2) ? 8704 : 8832;
    const int tilesPB = (lvl == 0) ? 4096 : (lvl == 1) ? 256 : (lvl == 2) ? 64 : 16;
    const int sh      = (lvl == 0) ? 4 : 6;
    unsigned char* fl = g_flags + fbase + b * tilesPB;

    for (int y = ya + (int)threadIdx.x; y <= yb; y += 64) {
        const int t0 = (y * H + xa) >> sh;
        const int t1 = (y * H + xb) >> sh;
        for (int t = t0; t <= t1; t++) fl[t] = 1;
    }
}

// -------------------------------------------------------------------------
// Lvl0 transpose: 64c x 16hw tiles (16-px skip granularity).
// grid = 2(b) * 4(cTile) * 4096(hwTile) = 32768 blocks, 256 threads.
// Load: thread = (channel, float4-group) -> 64B/row coalesced.
// Store: warp = hw row; lane = half2 channel pair -> 128B/row coalesced.
// -------------------------------------------------------------------------
__global__ __launch_bounds__(256) void k_transpose0(const float* __restrict__ p0) {
    __shared__ float tile[64][17];

    const int bid    = blockIdx.x;
    const int hwTile = bid & 4095;
    const int cTile  = (bid >> 12) & 3;
    const int b      = bid >> 14;

    if (g_flags[b * 4096 + hwTile] == 0) return;

    const int HW  = 65536;
    const int hw0 = hwTile << 4;
    const int c0  = cTile << 6;

    const int t = threadIdx.x;
    const int c = t >> 2;     // 0..63
    const int g = t & 3;      // float4 group within 16 hw

    const float* __restrict__ ip =
        p0 + (size_t)b * C_DIM * HW + (size_t)(c0 + c) * HW + hw0 + 4 * g;
    const float4 v = __ldcs((const float4*)ip);
    tile[c][4 * g + 0] = v.x;
    tile[c][4 * g + 1] = v.y;
    tile[c][4 * g + 2] = v.z;
    tile[c][4 * g + 3] = v.w;
    __syncthreads();

    __half* __restrict__ op =
        g_nhwc + (size_t)b * HW * C_DIM + (size_t)hw0 * C_DIM + c0;

    const int warp = t >> 5;
    const int lane = t & 31;
#pragma unroll
    for (int k = 0; k < 2; k++) {
        const int row = warp + 8 * k;
        const float a  = tile[2 * lane + 0][row];
        const float bb = tile[2 * lane + 1][row];
        ((half2*)(op + (size_t)row * C_DIM))[lane] = __floats2half2_rn(a, bb);
    }
}

// -------------------------------------------------------------------------
// Lvl1-3 transpose: 64c x 64hw tiles (as before).
// blocks: lvl1 2048 ([0,2048)), lvl2 512 ([2048,2560)), lvl3 128 ([2560,2688))
// -------------------------------------------------------------------------
__global__ __launch_bounds__(256) void k_transpose123(const float* __restrict__ p1,
                                                      const float* __restrict__ p2,
                                                      const float* __restrict__ p3) {
    __shared__ float tile[64][65];

    int bid = blockIdx.x;
    int lvl;
    const float* __restrict__ in;
    size_t base;
    int fbase, tilesPB;
    if (bid < 2048)      { lvl = 1; in = p1; base = 33554432ul; fbase = 8192; tilesPB = 256; }
    else if (bid < 2560) { lvl = 2; in = p2; base = 41943040ul; fbase = 8704; tilesPB = 64;  bid -= 2048; }
    else                 { lvl = 3; in = p3; base = 44040192ul; fbase = 8832; tilesPB = 16;  bid -= 2560; }

    const int Hs = 256 >> lvl;
    const int HW = Hs * Hs;
    const int hwTiles = HW >> 6;

    const int hwTile = bid % hwTiles;
    const int rest   = bid / hwTiles;
    const int cTile  = rest & 3;
    const int b      = rest >> 2;

    if (g_flags[fbase + b * tilesPB + hwTile] == 0) return;

    const int hw0 = hwTile << 6;
    const int c0  = cTile << 6;

    const int t  = threadIdx.x;
    const int tx = t & 15;    // hw group (float4)
    const int ty = t >> 4;    // c 0..15

    const float* __restrict__ ip =
        in + (size_t)b * C_DIM * HW + (size_t)c0 * HW + hw0;

#pragma unroll
    for (int k = 0; k < 4; k++) {
        const int c = ty + 16 * k;
        const float4 v = __ldcs((const float4*)(ip + (size_t)c * HW + 4 * tx));
        tile[c][4 * tx + 0] = v.x;
        tile[c][4 * tx + 1] = v.y;
        tile[c][4 * tx + 2] = v.z;
        tile[c][4 * tx + 3] = v.w;
    }
    __syncthreads();

    __half* __restrict__ op =
        g_nhwc + base + (size_t)b * HW * C_DIM + (size_t)hw0 * C_DIM + c0;

    const int c2 = t & 31;
    const int r0 = t >> 5;
#pragma unroll
    for (int k = 0; k < 8; k++) {
        const int row = r0 + 8 * k;
        const float a = tile[2 * c2 + 0][row];
        const float bfv = tile[2 * c2 + 1][row];
        ((half2*)(op + (size_t)row * C_DIM))[c2] = __floats2half2_rn(a, bfv);
    }
}

// -------------------------------------------------------------------------
// ROIAlign gather. Grid (512 rois, 4 chunks); each block does 64 channels.
// Per-sample 4-corner sum in half2 (HMUL2+3xHFMA2), fp32 cross-sample acc.
// -------------------------------------------------------------------------
__global__ __launch_bounds__(256) void k_gather(const float* __restrict__ boxes,
                                                float* __restrict__ out) {
    __shared__ int4  s_oq[196];           // 4 corner offsets
    __shared__ uint4 s_wq[196];           // 4 weights as packed half2 pairs
    __shared__ float s_out[NBIN * 66];    // [bin][64ch], pitch 66 (float2-safe)

    const int tid = threadIdx.x;
    const int roi = blockIdx.x;
    const int c0  = blockIdx.y << 6;      // 0,64,128,192
    const int b   = roi >> 8;             // N = 256 boxes per batch

    const float bx1 = __ldg(boxes + roi * 4 + 0);
    const float by1 = __ldg(boxes + roi * 4 + 1);
    const float bx2 = __ldg(boxes + roi * 4 + 2);
    const float by2 = __ldg(boxes + roi * 4 + 3);

    int lvl, H; float scale;
    roi_level(bx1, by1, bx2, by2, lvl, H, scale);

    const size_t base_off = ((lvl == 0) ? 0ul
                           : (lvl == 1) ? 33554432ul
                           : (lvl == 2) ? 41943040ul
                           :              44040192ul)
                          + (size_t)b * H * H * C_DIM;
    const __half* __restrict__ fb = g_nhwc + base_off + c0;

    const float x1s = bx1 * scale - 0.5f;
    const float y1s = by1 * scale - 0.5f;
    const float bw  = ((bx2 * scale - 0.5f) - x1s) * (1.0f / 7.0f);
    const float bh  = ((by2 * scale - 0.5f) - y1s) * (1.0f / 7.0f);

    if (tid < 196) {
        const int iy = tid / 14;
        const int ix = tid - iy * 14;
        const float ys = y1s + ((float)iy + 0.5f) * 0.5f * bh;
        const float xs = x1s + ((float)ix + 0.5f) * 0.5f * bw;
        const bool valid = (ys >= -1.0f) && (ys <= (float)H) &&
                           (xs >= -1.0f) && (xs <= (float)H);
        const float yc = fminf(fmaxf(ys, 0.0f), (float)(H - 1));
        const float xc = fminf(fmaxf(xs, 0.0f), (float)(H - 1));
        const int y0  = (int)floorf(yc);
        const int x0  = (int)floorf(xc);
        const int y1i = min(y0 + 1, H - 1);
        const int x1i = min(x0 + 1, H - 1);
        const float ly = yc - (float)y0, hy = 1.0f - ly;
        const float lx = xc - (float)x0, hx = 1.0f - lx;
        const float m = valid ? 0.25f : 0.0f;   // fold 2x2 mean
        const half2 w0 = __float2half2_rn(hy * hx * m);
        const half2 w1 = __float2half2_rn(hy * lx * m);
        const half2 w2 = __float2half2_rn(ly * hx * m);
        const half2 w3 = __float2half2_rn(ly * lx * m);
        uint4 wq;
        wq.x = *(const unsigned int*)&w0;
        wq.y = *(const unsigned int*)&w1;
        wq.z = *(const unsigned int*)&w2;
        wq.w = *(const unsigned int*)&w3;
        s_wq[tid] = wq;
        const int r0 = y0 * H, r1 = y1i * H;
        int4 oq;
        oq.x = (r0 + x0)  * C_DIM;
        oq.y = (r0 + x1i) * C_DIM;
        oq.z = (r1 + x0)  * C_DIM;
        oq.w = (r1 + x1i) * C_DIM;
        s_oq[tid] = oq;
    }
    __syncthreads();

    const int warp = tid >> 5;
    const int lane = tid & 31;
    const int cl   = lane << 1;           // channel pair within 64-ch chunk

    for (int bin = warp; bin < NBIN; bin += 8) {
        const int ph = bin / 7;
        const int pw = bin - ph * 7;
        float ax = 0.f, ay = 0.f;
#pragma unroll
        for (int sy = 0; sy < 2; sy++) {
#pragma unroll
            for (int sx = 0; sx < 2; sx++) {
                const int s = (ph * 2 + sy) * 14 + (pw * 2 + sx);
                const uint4 wq = s_wq[s];
                const int4  oq = s_oq[s];
                const half2 w0 = *(const half2*)&wq.x;
                const half2 w1 = *(const half2*)&wq.y;
                const half2 w2 = *(const half2*)&wq.z;
                const half2 w3 = *(const half2*)&wq.w;
                const half2 v0 = *(const half2*)(fb + oq.x + cl);
                const half2 v1 = *(const half2*)(fb + oq.y + cl);
                const half2 v2 = *(const half2*)(fb + oq.z + cl);
                const half2 v3 = *(const half2*)(fb + oq.w + cl);
                half2 acc = __hmul2(w0, v0);
                acc = __hfma2(w1, v1, acc);
                acc = __hfma2(w2, v2, acc);
                acc = __hfma2(w3, v3, acc);
                const float2 f = __half22float2(acc);
                ax += f.x;
                ay += f.y;
            }
        }
        *(float2*)(&s_out[bin * 66 + cl]) = make_float2(ax, ay);
    }
    __syncthreads();

    // Write [c0..c0+63][49] region — contiguous 3136 floats, coalesced.
    float* __restrict__ og = out + (size_t)roi * (C_DIM * NBIN) + (size_t)c0 * NBIN;
    for (int e = tid; e < 64 * NBIN; e += 256) {
        const int ch  = e / NBIN;
        const int bin = e - ch * NBIN;
        og[e] = s_out[bin * 66 + ch];
    }
}

// -------------------------------------------------------------------------
extern "C" void kernel_launch(void* const* d_in, const int* in_sizes, int n_in,
                              void* d_out, int out_size) {
    const float* x2 = (const float*)d_in[0];   // [2,256,256,256]
    const float* x3 = (const float*)d_in[1];   // [2,256,128,128]
    const float* x4 = (const float*)d_in[2];   // [2,256, 64, 64]
    const float* x5 = (const float*)d_in[3];   // [2,256, 32, 32]
    const float* boxes = (const float*)d_in[4];// [2,256,4]
    float* out = (float*)d_out;                // [512,256,7,7]

    void* flags_ptr = nullptr;
    cudaGetSymbolAddress(&flags_ptr, g_flags);
    cudaMemsetAsync(flags_ptr, 0, NFLAGS);     // async, graph-capturable

    k_mark<<<NROI, 64>>>(boxes);
    k_transpose0<<<32768, 256>>>(x2);
    k_transpose123<<<2688, 256>>>(x3, x4, x5);
    dim3 ggrid(NROI, 4);
    k_gather<<<ggrid, 256>>>(boxes, out);
}